// round 14
// baseline (speedup 1.0000x reference)
#include <cuda_runtime.h>
#include <cuda_fp16.h>
#include <cstdint>
#include <cstddef>

// Problem constants
#define NB 4096   // batch B
#define ND 768    // embedding D
#define NN 8192   // cat rows N
#define NS 4      // sources S

// ---------------- scratch (device globals; no allocations allowed) ----------
__device__ int8_t g_cat8[NN * ND];                     // 6 MB (s8, x16 scale)
__device__ int8_t g_x8[NB * ND];                       // 3 MB
__device__ __half g_conh[(size_t)NN * NB];             // 64 MB (fp16 con)
__device__ float g_s4part[128][NB];                    // norm4 partials
__device__ float g_inv_norm[NB];
__device__ float g_zpart[256][NB];                     // softmax denom partials
__device__ float g_wpart[256][NB];                     // y-weighted partials
__device__ float g_theta[NS][NB];

// ---------------- helpers ----------------------------------------------------
__device__ __forceinline__ uint32_t smem_u32(const void* p) {
    uint32_t a;
    asm("{ .reg .u64 t; cvta.to.shared.u64 t, %1; cvt.u32.u64 %0, t; }" : "=r"(a) : "l"(p));
    return a;
}

__device__ __forceinline__ void cp16(uint32_t smem, const void* gmem) {
    asm volatile("cp.async.cg.shared.global [%0], [%1], 16;\n" :: "r"(smem), "l"(gmem));
}

__device__ __forceinline__ void ldsm4(uint32_t* r, uint32_t addr) {
    asm volatile("ldmatrix.sync.aligned.m8n8.x4.shared.b16 {%0,%1,%2,%3}, [%4];"
                 : "=r"(r[0]), "=r"(r[1]), "=r"(r[2]), "=r"(r[3]) : "r"(addr));
}

// INT8 IMMA, m16n8k32, s32 accumulate (2x HMMA rate on legacy pipe)
__device__ __forceinline__ void mma16832(int* c, const uint32_t* a, const uint32_t* b) {
    asm volatile(
        "mma.sync.aligned.m16n8k32.row.col.s32.s8.s8.s32 "
        "{%0,%1,%2,%3}, {%4,%5,%6,%7}, {%8,%9}, {%0,%1,%2,%3};\n"
        : "+r"(c[0]), "+r"(c[1]), "+r"(c[2]), "+r"(c[3])
        : "r"(a[0]), "r"(a[1]), "r"(a[2]), "r"(a[3]), "r"(b[0]), "r"(b[1]));
}

// ---------------- convert fp32 -> s8 (x16 scale) ----------------------------
#define QSCALE 16.0f
#define DESCALE (1.0f / 256.0f)

__device__ __forceinline__ int8_t q8(float v) {
    int q = __float2int_rn(v * QSCALE);
    q = max(-127, min(127, q));
    return (int8_t)q;
}

__device__ __forceinline__ uint32_t pack_s8x4(float4 v) {
    uint32_t r;
    int8_t b0 = q8(v.x), b1 = q8(v.y), b2 = q8(v.z), b3 = q8(v.w);
    r = (uint8_t)b0 | ((uint32_t)(uint8_t)b1 << 8)
      | ((uint32_t)(uint8_t)b2 << 16) | ((uint32_t)(uint8_t)b3 << 24);
    return r;
}

__global__ void convert_kernel(const float* __restrict__ cat,
                               const float* __restrict__ x) {
    int i = blockIdx.x * blockDim.x + threadIdx.x;
    const int totCat = NN * ND / 4;
    const int totX   = NB * ND / 4;
    if (i < totCat) {
        ((uint32_t*)g_cat8)[i] = pack_s8x4(((const float4*)cat)[i]);
    } else if (i < totCat + totX) {
        int j = i - totCat;
        ((uint32_t*)g_x8)[j] = pack_s8x4(((const float4*)x)[j]);
    }
}

// ---------------- GEMM: con[N,B] = cat[N,D] @ x[B,D]^T  (INT8) --------------
// 128x128 CTA tile, 8 warps (2x4) at 64x32 each, K-chunk 64 bytes, 3-stage ring,
// 2 CTAs/SM.
#define BM 128
#define BN 128
#define BKB 64                  // s8 elements (= bytes) per K chunk
#define NKC (ND / BKB)          // 12
#define ST 3
#define ASTRB 80                // bytes per smem row (64 + 16 pad) — CF for ldsm & cp
#define A_BYTES (BM * ASTRB)    // 10240
#define B_BYTES (BN * ASTRB)    // 10240
#define B_OFF (ST * A_BYTES)    // 30720
#define SM_TOTAL (ST * (A_BYTES + B_BYTES))            // 61440
#define CSTR 136                // epilogue staging stride (halves)

__device__ __forceinline__ void load_chunk(uint32_t sbase, int kt, int s,
                                           int bm0, int bn0, int tid) {
    const int k0 = kt * BKB;
    #pragma unroll
    for (int t = 0; t < 2; t++) {            // A: 128 rows x 4 x 16B
        int idx = tid + t * 256;
        int row = idx >> 2, c = (idx & 3) * 16;
        const void* g = g_cat8 + (size_t)(bm0 + row) * ND + k0 + c;
        cp16(sbase + s * A_BYTES + row * ASTRB + c, g);
    }
    #pragma unroll
    for (int t = 0; t < 2; t++) {            // B: 128 rows x 4 x 16B
        int idx = tid + t * 256;
        int row = idx >> 2, c = (idx & 3) * 16;
        const void* g = g_x8 + (size_t)(bn0 + row) * ND + k0 + c;
        cp16(sbase + B_OFF + s * B_BYTES + row * ASTRB + c, g);
    }
    asm volatile("cp.async.commit_group;\n" ::: "memory");
}

__global__ void __launch_bounds__(256, 2) gemm_kernel() {
    extern __shared__ char smem[];
    const uint32_t sbase = smem_u32(smem);

    const int tid  = threadIdx.x;
    const int lane = tid & 31;
    const int warp = tid >> 5;
    const int wm   = warp & 1;     // 2 warp rows (64 each)
    const int wn   = warp >> 1;    // 4 warp cols (32 each)
    const int bm0  = blockIdx.y * BM;    // n offset
    const int bn0  = blockIdx.x * BN;    // b offset

    const int lr = lane & 15;            // ldmatrix row within 16-row tile
    const int lh = (lane >> 4) * 16;     // 16-byte half select

    int acc[4][4][4];
    #pragma unroll
    for (int mt = 0; mt < 4; mt++)
        #pragma unroll
        for (int nt = 0; nt < 4; nt++)
            #pragma unroll
            for (int k = 0; k < 4; k++) acc[mt][nt][k] = 0;

    load_chunk(sbase, 0, 0, bm0, bn0, tid);
    load_chunk(sbase, 1, 1, bm0, bn0, tid);

    for (int kt = 0; kt < NKC; kt++) {
        const int s = kt % ST;
        if (kt < NKC - 1) asm volatile("cp.async.wait_group 1;\n" ::: "memory");
        else              asm volatile("cp.async.wait_group 0;\n" ::: "memory");
        __syncthreads();

        if (kt + 2 < NKC)
            load_chunk(sbase, kt + 2, (kt + 2) % ST, bm0, bn0, tid);

        #pragma unroll
        for (int ks = 0; ks < 2; ks++) {     // two k32 steps per 64-byte chunk
            uint32_t af[4][4], bb[2][4];
            const uint32_t abase =
                sbase + s * A_BYTES + (wm * 64 + lr) * ASTRB + ks * 32 + lh;
            #pragma unroll
            for (int mt = 0; mt < 4; mt++)
                ldsm4(af[mt], abase + mt * 16 * ASTRB);
            const uint32_t bbase =
                sbase + B_OFF + s * B_BYTES + (wn * 32 + lr) * ASTRB + ks * 32 + lh;
            #pragma unroll
            for (int p = 0; p < 2; p++)
                ldsm4(bb[p], bbase + p * 16 * ASTRB);

            #pragma unroll
            for (int mt = 0; mt < 4; mt++)
                #pragma unroll
                for (int nt = 0; nt < 4; nt++) {
                    uint32_t bfr[2] = { bb[nt >> 1][nt & 1], bb[nt >> 1][2 + (nt & 1)] };
                    mma16832(acc[mt][nt], af[mt], bfr);
                }
        }
    }

    // descale to float (inputs were x16 each; s32 accumulation is exact)
    float facc[4][4][4];
    #pragma unroll
    for (int mt = 0; mt < 4; mt++)
        #pragma unroll
        for (int nt = 0; nt < 4; nt++)
            #pragma unroll
            for (int k = 0; k < 4; k++)
                facc[mt][nt][k] = (float)acc[mt][nt][k] * DESCALE;

    // ---- fused per-column sum(v^4) over this warp's 64 rows ----
    #pragma unroll
    for (int nt = 0; nt < 4; nt++) {
        float se = 0.f, so = 0.f;
        #pragma unroll
        for (int mt = 0; mt < 4; mt++) {
            float a0 = facc[mt][nt][0], a1 = facc[mt][nt][1];
            float a2 = facc[mt][nt][2], a3 = facc[mt][nt][3];
            se = fmaf(a0 * a0, a0 * a0, se); se = fmaf(a2 * a2, a2 * a2, se);
            so = fmaf(a1 * a1, a1 * a1, so); so = fmaf(a3 * a3, a3 * a3, so);
        }
        #pragma unroll
        for (int m = 4; m <= 16; m <<= 1) {   // reduce over lane>>2 (same lane&3)
            se += __shfl_xor_sync(0xffffffffu, se, m);
            so += __shfl_xor_sync(0xffffffffu, so, m);
        }
        if (lane < 4) {
            int c = bn0 + wn * 32 + nt * 8 + lane * 2;
            int slot = blockIdx.y * 2 + wm;
            g_s4part[slot][c]     = se;
            g_s4part[slot][c + 1] = so;
        }
    }

    // ---- epilogue: stage fp16 tile in smem, write coalesced rows ----
    __syncthreads();                       // smem ring no longer needed
    __half* sst = (__half*)smem;
    #pragma unroll
    for (int mt = 0; mt < 4; mt++) {
        #pragma unroll
        for (int nt = 0; nt < 4; nt++) {
            const int r = wm * 64 + mt * 16 + (lane >> 2);
            const int c = wn * 32 + nt * 8 + (lane & 3) * 2;
            *(__half2*)&sst[r * CSTR + c] =
                __floats2half2_rn(facc[mt][nt][0], facc[mt][nt][1]);
            *(__half2*)&sst[(r + 8) * CSTR + c] =
                __floats2half2_rn(facc[mt][nt][2], facc[mt][nt][3]);
        }
    }
    __syncthreads();
    #pragma unroll
    for (int i = 0; i < 16; i++) {
        const int r = warp * 16 + i;
        uint2 v = *(const uint2*)&sst[r * CSTR + lane * 4];
        *(uint2*)&g_conh[(size_t)(bm0 + r) * NB + bn0 + lane * 4] = v;
    }
}

// ---------------- theta + norm finalize (fused launch) ----------------------
__global__ void theta_norm_kernel(const float* __restrict__ x,
                                  const float* __restrict__ phi) {
    if (blockIdx.x >= 512) {
        int b = (blockIdx.x - 512) * 256 + threadIdx.x;
        float s = 0.f;
        #pragma unroll
        for (int i = 0; i < 128; i++) s += g_s4part[i][b];
        float nrm = sqrtf(sqrtf(s));
        nrm = fmaxf(nrm, 1e-12f);
        g_inv_norm[b] = 1.0f / nrm;
        return;
    }
    const int warp = threadIdx.x >> 5;
    const int lane = threadIdx.x & 31;
    const int b = blockIdx.x * 8 + warp;
    const float* xr = x + (size_t)b * ND;
    float xv[24];
    #pragma unroll
    for (int i = 0; i < 24; i++) xv[i] = xr[lane + i * 32];
    #pragma unroll
    for (int s = 0; s < NS; s++) {
        const float* pr = phi + (size_t)s * ND;
        float acc = 0.f;
        #pragma unroll
        for (int i = 0; i < 24; i++) acc = fmaf(xv[i], pr[lane + i * 32], acc);
        #pragma unroll
        for (int off = 16; off; off >>= 1) acc += __shfl_xor_sync(0xffffffffu, acc, off);
        if (lane == 0) g_theta[s][b] = expf(acc);
    }
}

// ---------------- pass B: per-column exp sums (Z, y-weighted) ---------------
// 4 columns per thread, 32 rows per block. grid (NB/1024, NN/32) = (4, 256).
__global__ void exp_pass(const int* __restrict__ y) {
    const int b0 = blockIdx.x * 1024 + threadIdx.x * 4;
    const int n0 = blockIdx.y * 32;
    const float4 inv = *(const float4*)&g_inv_norm[b0];
    const __half* p = g_conh + (size_t)n0 * NB + b0;
    float z0 = 0.f, z1 = 0.f, z2 = 0.f, z3 = 0.f;
    float w0 = 0.f, w1 = 0.f, w2 = 0.f, w3 = 0.f;
    #pragma unroll 4
    for (int i = 0; i < 32; i++) {
        uint2 v = *(const uint2*)(p + (size_t)i * NB);
        __half2 h01 = *reinterpret_cast<__half2*>(&v.x);
        __half2 h23 = *reinterpret_cast<__half2*>(&v.y);
        float2 f01 = __half22float2(h01);
        float2 f23 = __half22float2(h23);
        float m = (float)__ldg(&y[n0 + i]);
        float e0 = __expf(f01.x * inv.x);
        float e1 = __expf(f01.y * inv.y);
        float e2 = __expf(f23.x * inv.z);
        float e3 = __expf(f23.y * inv.w);
        z0 += e0; z1 += e1; z2 += e2; z3 += e3;
        w0 = fmaf(m, e0, w0); w1 = fmaf(m, e1, w1);
        w2 = fmaf(m, e2, w2); w3 = fmaf(m, e3, w3);
    }
    *(float4*)&g_zpart[blockIdx.y][b0] = make_float4(z0, z1, z2, z3);
    *(float4*)&g_wpart[blockIdx.y][b0] = make_float4(w0, w1, w2, w3);
}

// ---------------- final: sigmoid( sum_s theta*wsum / Z + bias ) -------------
__global__ void final_kernel(const float* __restrict__ bias, float* __restrict__ out) {
    int b = blockIdx.x * 256 + threadIdx.x;
    float Z = 0.f;
    #pragma unroll
    for (int i = 0; i < 256; i++) Z += g_zpart[i][b];
    float sum = 0.f;
    #pragma unroll
    for (int s = 0; s < NS; s++) {
        float w = 0.f;
        #pragma unroll
        for (int i = 0; i < 64; i++) w += g_wpart[s * 64 + i][b];
        sum += w * g_theta[s][b];
    }
    float r = sum / Z + bias[0];
    out[b] = 1.0f / (1.0f + expf(-r));
}

// ---------------- launch -----------------------------------------------------
extern "C" void kernel_launch(void* const* d_in, const int* in_sizes, int n_in,
                              void* d_out, int out_size) {
    const float* x = nullptr; const float* cat = nullptr; const float* phi = nullptr;
    const float* bias = nullptr; const int* y = nullptr;
    for (int i = 0; i < n_in; i++) {
        switch (in_sizes[i]) {
            case NB * ND: x    = (const float*)d_in[i]; break;
            case NN * ND: cat  = (const float*)d_in[i]; break;
            case NN:      y    = (const int*)d_in[i];   break;
            case NS * ND: phi  = (const float*)d_in[i]; break;
            case 1:       bias = (const float*)d_in[i]; break;
            default: break;
        }
    }
    float* out = (float*)d_out;

    cudaFuncSetAttribute(gemm_kernel, cudaFuncAttributeMaxDynamicSharedMemorySize, SM_TOTAL);

    const int tot4 = (NN * ND + NB * ND) / 4;
    convert_kernel<<<(tot4 + 255) / 256, 256>>>(cat, x);
    gemm_kernel<<<dim3(NB / BN, NN / BM), 256, SM_TOTAL>>>();
    theta_norm_kernel<<<528, 256>>>(x, phi);
    exp_pass<<<dim3(NB / 1024, NN / 32), 256>>>(y);
    final_kernel<<<NB / 256, 256>>>(bias, out);
}

// round 15
// speedup vs baseline: 1.8796x; 1.8796x over previous
#include <cuda_runtime.h>
#include <cuda_fp16.h>
#include <cuda_fp8.h>
#include <cstdint>
#include <cstddef>

// Problem constants
#define NB 4096   // batch B
#define ND 768    // embedding D
#define NN 8192   // cat rows N
#define NS 4      // sources S

// ---------------- scratch (device globals; no allocations allowed) ----------
__device__ uint8_t g_cat8[NN * ND];                    // 6 MB (e4m3, x16 scale)
__device__ uint8_t g_x8[NB * ND];                      // 3 MB
__device__ __half g_conh[(size_t)NN * NB];             // 64 MB (fp16 con)
__device__ float g_s4part[128][NB];                    // norm4 partials
__device__ float g_inv_norm[NB];
__device__ float g_zpart[256][NB];                     // softmax denom partials
__device__ float g_wpart[256][NB];                     // y-weighted partials
__device__ float g_theta[NS][NB];

// ---------------- helpers ----------------------------------------------------
__device__ __forceinline__ uint32_t smem_u32(const void* p) {
    uint32_t a;
    asm("{ .reg .u64 t; cvta.to.shared.u64 t, %1; cvt.u32.u64 %0, t; }" : "=r"(a) : "l"(p));
    return a;
}

__device__ __forceinline__ void cp16(uint32_t smem, const void* gmem) {
    asm volatile("cp.async.cg.shared.global [%0], [%1], 16;\n" :: "r"(smem), "l"(gmem));
}

__device__ __forceinline__ void ldsm4(uint32_t* r, uint32_t addr) {
    asm volatile("ldmatrix.sync.aligned.m8n8.x4.shared.b16 {%0,%1,%2,%3}, [%4];"
                 : "=r"(r[0]), "=r"(r[1]), "=r"(r[2]), "=r"(r[3]) : "r"(addr));
}

// FP8 e4m3 MMA, m16n8k32, fp32 accumulate (fastest legacy tensor path on sm_103)
__device__ __forceinline__ void mma16832(float* c, const uint32_t* a, const uint32_t* b) {
    asm volatile(
        "mma.sync.aligned.m16n8k32.row.col.f32.e4m3.e4m3.f32 "
        "{%0,%1,%2,%3}, {%4,%5,%6,%7}, {%8,%9}, {%0,%1,%2,%3};\n"
        : "+f"(c[0]), "+f"(c[1]), "+f"(c[2]), "+f"(c[3])
        : "r"(a[0]), "r"(a[1]), "r"(a[2]), "r"(a[3]), "r"(b[0]), "r"(b[1]));
}

// ---------------- convert fp32 -> e4m3 (x16 scale) --------------------------
#define QSCALE 16.0f
#define DESCALE (1.0f / 256.0f)

__device__ __forceinline__ uint32_t pack_fp8x4(float4 v) {
    __nv_fp8x2_storage_t lo = __nv_cvt_float2_to_fp8x2(
        make_float2(v.x * QSCALE, v.y * QSCALE), __NV_SATFINITE, __NV_E4M3);
    __nv_fp8x2_storage_t hi = __nv_cvt_float2_to_fp8x2(
        make_float2(v.z * QSCALE, v.w * QSCALE), __NV_SATFINITE, __NV_E4M3);
    return (uint32_t)lo | ((uint32_t)hi << 16);
}

__global__ void convert_kernel(const float* __restrict__ cat,
                               const float* __restrict__ x) {
    int i = blockIdx.x * blockDim.x + threadIdx.x;
    const int totCat = NN * ND / 4;
    const int totX   = NB * ND / 4;
    if (i < totCat) {
        ((uint32_t*)g_cat8)[i] = pack_fp8x4(((const float4*)cat)[i]);
    } else if (i < totCat + totX) {
        int j = i - totCat;
        ((uint32_t*)g_x8)[j] = pack_fp8x4(((const float4*)x)[j]);
    }
}

// ---------------- GEMM: con[N,B] = cat[N,D] @ x[B,D]^T  (FP8) ---------------
// 128x128 CTA tile, 8 warps (2x4) at 64x32 each, K-chunk 64 fp8, 3-stage ring,
// 2 CTAs/SM.
#define BM 128
#define BN 128
#define BKB 64                  // fp8 elements (= bytes) per K chunk
#define NKC (ND / BKB)          // 12
#define ST 3
#define ASTRB 80                // bytes per smem row (64 + 16 pad) — CF for ldsm & cp
#define A_BYTES (BM * ASTRB)    // 10240
#define B_BYTES (BN * ASTRB)    // 10240
#define B_OFF (ST * A_BYTES)    // 30720
#define SM_TOTAL (ST * (A_BYTES + B_BYTES))            // 61440
#define CSTR 136                // epilogue staging stride (halves)

__device__ __forceinline__ void load_chunk(uint32_t sbase, int kt, int s,
                                           int bm0, int bn0, int tid) {
    const int k0 = kt * BKB;
    #pragma unroll
    for (int t = 0; t < 2; t++) {            // A: 128 rows x 4 x 16B
        int idx = tid + t * 256;
        int row = idx >> 2, c = (idx & 3) * 16;
        const void* g = g_cat8 + (size_t)(bm0 + row) * ND + k0 + c;
        cp16(sbase + s * A_BYTES + row * ASTRB + c, g);
    }
    #pragma unroll
    for (int t = 0; t < 2; t++) {            // B: 128 rows x 4 x 16B
        int idx = tid + t * 256;
        int row = idx >> 2, c = (idx & 3) * 16;
        const void* g = g_x8 + (size_t)(bn0 + row) * ND + k0 + c;
        cp16(sbase + B_OFF + s * B_BYTES + row * ASTRB + c, g);
    }
    asm volatile("cp.async.commit_group;\n" ::: "memory");
}

__global__ void __launch_bounds__(256, 2) gemm_kernel() {
    extern __shared__ char smem[];
    const uint32_t sbase = smem_u32(smem);

    const int tid  = threadIdx.x;
    const int lane = tid & 31;
    const int warp = tid >> 5;
    const int wm   = warp & 1;     // 2 warp rows (64 each)
    const int wn   = warp >> 1;    // 4 warp cols (32 each)
    const int bm0  = blockIdx.y * BM;    // n offset
    const int bn0  = blockIdx.x * BN;    // b offset

    const int lr = lane & 15;            // ldmatrix row within 16-row tile
    const int lh = (lane >> 4) * 16;     // 16-byte half select

    float acc[4][4][4];
    #pragma unroll
    for (int mt = 0; mt < 4; mt++)
        #pragma unroll
        for (int nt = 0; nt < 4; nt++)
            #pragma unroll
            for (int k = 0; k < 4; k++) acc[mt][nt][k] = 0.f;

    load_chunk(sbase, 0, 0, bm0, bn0, tid);
    load_chunk(sbase, 1, 1, bm0, bn0, tid);

    for (int kt = 0; kt < NKC; kt++) {
        const int s = kt % ST;
        if (kt < NKC - 1) asm volatile("cp.async.wait_group 1;\n" ::: "memory");
        else              asm volatile("cp.async.wait_group 0;\n" ::: "memory");
        __syncthreads();

        if (kt + 2 < NKC)
            load_chunk(sbase, kt + 2, (kt + 2) % ST, bm0, bn0, tid);

        #pragma unroll
        for (int ks = 0; ks < 2; ks++) {     // two k32 steps per 64-byte chunk
            uint32_t af[4][4], bb[2][4];
            const uint32_t abase =
                sbase + s * A_BYTES + (wm * 64 + lr) * ASTRB + ks * 32 + lh;
            #pragma unroll
            for (int mt = 0; mt < 4; mt++)
                ldsm4(af[mt], abase + mt * 16 * ASTRB);
            const uint32_t bbase =
                sbase + B_OFF + s * B_BYTES + (wn * 32 + lr) * ASTRB + ks * 32 + lh;
            #pragma unroll
            for (int p = 0; p < 2; p++)
                ldsm4(bb[p], bbase + p * 16 * ASTRB);

            #pragma unroll
            for (int mt = 0; mt < 4; mt++)
                #pragma unroll
                for (int nt = 0; nt < 4; nt++) {
                    uint32_t bfr[2] = { bb[nt >> 1][nt & 1], bb[nt >> 1][2 + (nt & 1)] };
                    mma16832(acc[mt][nt], af[mt], bfr);
                }
        }
    }

    // descale (inputs were x16 each)
    #pragma unroll
    for (int mt = 0; mt < 4; mt++)
        #pragma unroll
        for (int nt = 0; nt < 4; nt++)
            #pragma unroll
            for (int k = 0; k < 4; k++) acc[mt][nt][k] *= DESCALE;

    // ---- fused per-column sum(v^4) over this warp's 64 rows ----
    #pragma unroll
    for (int nt = 0; nt < 4; nt++) {
        float se = 0.f, so = 0.f;
        #pragma unroll
        for (int mt = 0; mt < 4; mt++) {
            float a0 = acc[mt][nt][0], a1 = acc[mt][nt][1];
            float a2 = acc[mt][nt][2], a3 = acc[mt][nt][3];
            se = fmaf(a0 * a0, a0 * a0, se); se = fmaf(a2 * a2, a2 * a2, se);
            so = fmaf(a1 * a1, a1 * a1, so); so = fmaf(a3 * a3, a3 * a3, so);
        }
        #pragma unroll
        for (int m = 4; m <= 16; m <<= 1) {   // reduce over lane>>2 (same lane&3)
            se += __shfl_xor_sync(0xffffffffu, se, m);
            so += __shfl_xor_sync(0xffffffffu, so, m);
        }
        if (lane < 4) {
            int c = bn0 + wn * 32 + nt * 8 + lane * 2;
            int slot = blockIdx.y * 2 + wm;
            g_s4part[slot][c]     = se;
            g_s4part[slot][c + 1] = so;
        }
    }

    // ---- epilogue: stage fp16 tile in smem, write coalesced rows ----
    __syncthreads();                       // smem ring no longer needed
    __half* sst = (__half*)smem;
    #pragma unroll
    for (int mt = 0; mt < 4; mt++) {
        #pragma unroll
        for (int nt = 0; nt < 4; nt++) {
            const int r = wm * 64 + mt * 16 + (lane >> 2);
            const int c = wn * 32 + nt * 8 + (lane & 3) * 2;
            *(__half2*)&sst[r * CSTR + c] =
                __floats2half2_rn(acc[mt][nt][0], acc[mt][nt][1]);
            *(__half2*)&sst[(r + 8) * CSTR + c] =
                __floats2half2_rn(acc[mt][nt][2], acc[mt][nt][3]);
        }
    }
    __syncthreads();
    #pragma unroll
    for (int i = 0; i < 16; i++) {
        const int r = warp * 16 + i;
        uint2 v = *(const uint2*)&sst[r * CSTR + lane * 4];
        *(uint2*)&g_conh[(size_t)(bm0 + r) * NB + bn0 + lane * 4] = v;
    }
}

// ---------------- theta + norm finalize (fused launch) ----------------------
__global__ void theta_norm_kernel(const float* __restrict__ x,
                                  const float* __restrict__ phi) {
    if (blockIdx.x >= 512) {
        int b = (blockIdx.x - 512) * 256 + threadIdx.x;
        float s = 0.f;
        #pragma unroll
        for (int i = 0; i < 128; i++) s += g_s4part[i][b];
        float nrm = sqrtf(sqrtf(s));
        nrm = fmaxf(nrm, 1e-12f);
        g_inv_norm[b] = 1.0f / nrm;
        return;
    }
    const int warp = threadIdx.x >> 5;
    const int lane = threadIdx.x & 31;
    const int b = blockIdx.x * 8 + warp;
    const float* xr = x + (size_t)b * ND;
    float xv[24];
    #pragma unroll
    for (int i = 0; i < 24; i++) xv[i] = xr[lane + i * 32];
    #pragma unroll
    for (int s = 0; s < NS; s++) {
        const float* pr = phi + (size_t)s * ND;
        float acc = 0.f;
        #pragma unroll
        for (int i = 0; i < 24; i++) acc = fmaf(xv[i], pr[lane + i * 32], acc);
        #pragma unroll
        for (int off = 16; off; off >>= 1) acc += __shfl_xor_sync(0xffffffffu, acc, off);
        if (lane == 0) g_theta[s][b] = expf(acc);
    }
}

// ---------------- pass B: per-column exp sums (Z, y-weighted) ---------------
// 4 columns per thread, 32 rows per block. grid (NB/1024, NN/32) = (4, 256).
__global__ void exp_pass(const int* __restrict__ y) {
    __shared__ float sy[32];
    if (threadIdx.x < 32) sy[threadIdx.x] = (float)__ldg(&y[blockIdx.y * 32 + threadIdx.x]);
    __syncthreads();

    const int b0 = blockIdx.x * 1024 + threadIdx.x * 4;
    const int n0 = blockIdx.y * 32;
    const float4 inv = *(const float4*)&g_inv_norm[b0];
    const __half* p = g_conh + (size_t)n0 * NB + b0;
    float z0 = 0.f, z1 = 0.f, z2 = 0.f, z3 = 0.f;
    float w0 = 0.f, w1 = 0.f, w2 = 0.f, w3 = 0.f;
    #pragma unroll 4
    for (int i = 0; i < 32; i++) {
        uint2 v = *(const uint2*)(p + (size_t)i * NB);
        __half2 h01 = *reinterpret_cast<__half2*>(&v.x);
        __half2 h23 = *reinterpret_cast<__half2*>(&v.y);
        float2 f01 = __half22float2(h01);
        float2 f23 = __half22float2(h23);
        float m = sy[i];
        float e0 = __expf(f01.x * inv.x);
        float e1 = __expf(f01.y * inv.y);
        float e2 = __expf(f23.x * inv.z);
        float e3 = __expf(f23.y * inv.w);
        z0 += e0; z1 += e1; z2 += e2; z3 += e3;
        w0 = fmaf(m, e0, w0); w1 = fmaf(m, e1, w1);
        w2 = fmaf(m, e2, w2); w3 = fmaf(m, e3, w3);
    }
    *(float4*)&g_zpart[blockIdx.y][b0] = make_float4(z0, z1, z2, z3);
    *(float4*)&g_wpart[blockIdx.y][b0] = make_float4(w0, w1, w2, w3);
}

// ---------------- final: sigmoid( sum_s theta*wsum / Z + bias ) -------------
__global__ void final_kernel(const float* __restrict__ bias, float* __restrict__ out) {
    int b = blockIdx.x * 256 + threadIdx.x;
    float Z = 0.f;
    #pragma unroll
    for (int i = 0; i < 256; i++) Z += g_zpart[i][b];
    float sum = 0.f;
    #pragma unroll
    for (int s = 0; s < NS; s++) {
        float w = 0.f;
        #pragma unroll
        for (int i = 0; i < 64; i++) w += g_wpart[s * 64 + i][b];
        sum += w * g_theta[s][b];
    }
    float r = sum / Z + bias[0];
    out[b] = 1.0f / (1.0f + expf(-r));
}

// ---------------- launch -----------------------------------------------------
extern "C" void kernel_launch(void* const* d_in, const int* in_sizes, int n_in,
                              void* d_out, int out_size) {
    const float* x = nullptr; const float* cat = nullptr; const float* phi = nullptr;
    const float* bias = nullptr; const int* y = nullptr;
    for (int i = 0; i < n_in; i++) {
        switch (in_sizes[i]) {
            case NB * ND: x    = (const float*)d_in[i]; break;
            case NN * ND: cat  = (const float*)d_in[i]; break;
            case NN:      y    = (const int*)d_in[i];   break;
            case NS * ND: phi  = (const float*)d_in[i]; break;
            case 1:       bias = (const float*)d_in[i]; break;
            default: break;
        }
    }
    float* out = (float*)d_out;

    cudaFuncSetAttribute(gemm_kernel, cudaFuncAttributeMaxDynamicSharedMemorySize, SM_TOTAL);

    const int tot4 = (NN * ND + NB * ND) / 4;
    convert_kernel<<<(tot4 + 255) / 256, 256>>>(cat, x);
    gemm_kernel<<<dim3(NB / BN, NN / BM), 256, SM_TOTAL>>>();
    theta_norm_kernel<<<528, 256>>>(x, phi);
    exp_pass<<<dim3(NB / 1024, NN / 32), 256>>>(y);
    final_kernel<<<NB / 256, 256>>>(bias, out);
}

// round 16
// speedup vs baseline: 1.8966x; 1.0090x over previous
#include <cuda_runtime.h>
#include <cuda_fp16.h>
#include <cuda_fp8.h>
#include <cstdint>
#include <cstddef>

// Problem constants
#define NB 4096   // batch B
#define ND 768    // embedding D
#define NN 8192   // cat rows N
#define NS 4      // sources S

// ---------------- scratch (device globals; no allocations allowed) ----------
__device__ uint8_t g_cat8[NN * ND];                    // 6 MB (e4m3, x16 scale)
__device__ uint8_t g_x8[NB * ND];                      // 3 MB
__device__ __half g_conh[(size_t)NN * NB];             // 64 MB (fp16 con)
__device__ float g_s4part[128][NB];                    // norm4 partials
__device__ float g_inv_norm[NB];
__device__ float g_zpart[256][NB];                     // softmax denom partials
__device__ float g_wpart[256][NB];                     // y-weighted partials
__device__ float g_theta[NS][NB];

// ---------------- helpers ----------------------------------------------------
__device__ __forceinline__ uint32_t smem_u32(const void* p) {
    uint32_t a;
    asm("{ .reg .u64 t; cvta.to.shared.u64 t, %1; cvt.u32.u64 %0, t; }" : "=r"(a) : "l"(p));
    return a;
}

__device__ __forceinline__ void cp16(uint32_t smem, const void* gmem) {
    asm volatile("cp.async.cg.shared.global [%0], [%1], 16;\n" :: "r"(smem), "l"(gmem));
}

__device__ __forceinline__ void ldsm4(uint32_t* r, uint32_t addr) {
    asm volatile("ldmatrix.sync.aligned.m8n8.x4.shared.b16 {%0,%1,%2,%3}, [%4];"
                 : "=r"(r[0]), "=r"(r[1]), "=r"(r[2]), "=r"(r[3]) : "r"(addr));
}

// FP8 e4m3 MMA, m16n8k32, fp32 accumulate (fastest legacy tensor path on sm_103)
__device__ __forceinline__ void mma16832(float* c, const uint32_t* a, const uint32_t* b) {
    asm volatile(
        "mma.sync.aligned.m16n8k32.row.col.f32.e4m3.e4m3.f32 "
        "{%0,%1,%2,%3}, {%4,%5,%6,%7}, {%8,%9}, {%0,%1,%2,%3};\n"
        : "+f"(c[0]), "+f"(c[1]), "+f"(c[2]), "+f"(c[3])
        : "r"(a[0]), "r"(a[1]), "r"(a[2]), "r"(a[3]), "r"(b[0]), "r"(b[1]));
}

__device__ __forceinline__ __half2 hex2(__half2 v) {
    __half2 r;
    asm("ex2.approx.f16x2 %0, %1;"
        : "=r"(*reinterpret_cast<uint32_t*>(&r))
        : "r"(*reinterpret_cast<const uint32_t*>(&v)));
    return r;
}

// ---------------- convert fp32 -> e4m3 (x16 scale) + theta ------------------
#define QSCALE 16.0f
#define DESCALE (1.0f / 256.0f)
#define NCONV ((NN * ND + NB * ND) / 4 / 256)   // 9216 convert blocks

__device__ __forceinline__ uint32_t pack_fp8x4(float4 v) {
    __nv_fp8x2_storage_t lo = __nv_cvt_float2_to_fp8x2(
        make_float2(v.x * QSCALE, v.y * QSCALE), __NV_SATFINITE, __NV_E4M3);
    __nv_fp8x2_storage_t hi = __nv_cvt_float2_to_fp8x2(
        make_float2(v.z * QSCALE, v.w * QSCALE), __NV_SATFINITE, __NV_E4M3);
    return (uint32_t)lo | ((uint32_t)hi << 16);
}

__global__ void convert_theta_kernel(const float* __restrict__ cat,
                                     const float* __restrict__ x,
                                     const float* __restrict__ phi) {
    if (blockIdx.x >= NCONV) {
        // theta: one warp per batch column; 512 blocks x 8 warps = 4096
        const int warp = threadIdx.x >> 5;
        const int lane = threadIdx.x & 31;
        const int b = (blockIdx.x - NCONV) * 8 + warp;
        const float* xr = x + (size_t)b * ND;
        float xv[24];
        #pragma unroll
        for (int i = 0; i < 24; i++) xv[i] = xr[lane + i * 32];
        #pragma unroll
        for (int s = 0; s < NS; s++) {
            const float* pr = phi + (size_t)s * ND;
            float acc = 0.f;
            #pragma unroll
            for (int i = 0; i < 24; i++) acc = fmaf(xv[i], pr[lane + i * 32], acc);
            #pragma unroll
            for (int off = 16; off; off >>= 1)
                acc += __shfl_xor_sync(0xffffffffu, acc, off);
            if (lane == 0) g_theta[s][b] = expf(acc);
        }
        return;
    }
    int i = blockIdx.x * blockDim.x + threadIdx.x;
    const int totCat = NN * ND / 4;
    if (i < totCat) {
        ((uint32_t*)g_cat8)[i] = pack_fp8x4(((const float4*)cat)[i]);
    } else {
        int j = i - totCat;
        ((uint32_t*)g_x8)[j] = pack_fp8x4(((const float4*)x)[j]);
    }
}

// ---------------- GEMM: con[N,B] = cat[N,D] @ x[B,D]^T  (FP8) ---------------
// 128x128 CTA tile, 8 warps (2x4) at 64x32 each, K-chunk 64 fp8, 3-stage ring,
// 2 CTAs/SM.
#define BM 128
#define BN 128
#define BKB 64                  // fp8 elements (= bytes) per K chunk
#define NKC (ND / BKB)          // 12
#define ST 3
#define ASTRB 80                // bytes per smem row (64 + 16 pad) — CF for ldsm & cp
#define A_BYTES (BM * ASTRB)    // 10240
#define B_BYTES (BN * ASTRB)    // 10240
#define B_OFF (ST * A_BYTES)    // 30720
#define SM_TOTAL (ST * (A_BYTES + B_BYTES))            // 61440
#define CSTR 136                // epilogue staging stride (halves)

__device__ __forceinline__ void load_chunk(uint32_t sbase, int kt, int s,
                                           int bm0, int bn0, int tid) {
    const int k0 = kt * BKB;
    #pragma unroll
    for (int t = 0; t < 2; t++) {            // A: 128 rows x 4 x 16B
        int idx = tid + t * 256;
        int row = idx >> 2, c = (idx & 3) * 16;
        const void* g = g_cat8 + (size_t)(bm0 + row) * ND + k0 + c;
        cp16(sbase + s * A_BYTES + row * ASTRB + c, g);
    }
    #pragma unroll
    for (int t = 0; t < 2; t++) {            // B: 128 rows x 4 x 16B
        int idx = tid + t * 256;
        int row = idx >> 2, c = (idx & 3) * 16;
        const void* g = g_x8 + (size_t)(bn0 + row) * ND + k0 + c;
        cp16(sbase + B_OFF + s * B_BYTES + row * ASTRB + c, g);
    }
    asm volatile("cp.async.commit_group;\n" ::: "memory");
}

__global__ void __launch_bounds__(256, 2) gemm_kernel() {
    extern __shared__ char smem[];
    const uint32_t sbase = smem_u32(smem);

    const int tid  = threadIdx.x;
    const int lane = tid & 31;
    const int warp = tid >> 5;
    const int wm   = warp & 1;     // 2 warp rows (64 each)
    const int wn   = warp >> 1;    // 4 warp cols (32 each)
    const int bm0  = blockIdx.y * BM;    // n offset
    const int bn0  = blockIdx.x * BN;    // b offset

    const int lr = lane & 15;            // ldmatrix row within 16-row tile
    const int lh = (lane >> 4) * 16;     // 16-byte half select

    float acc[4][4][4];
    #pragma unroll
    for (int mt = 0; mt < 4; mt++)
        #pragma unroll
        for (int nt = 0; nt < 4; nt++)
            #pragma unroll
            for (int k = 0; k < 4; k++) acc[mt][nt][k] = 0.f;

    load_chunk(sbase, 0, 0, bm0, bn0, tid);
    load_chunk(sbase, 1, 1, bm0, bn0, tid);

    for (int kt = 0; kt < NKC; kt++) {
        const int s = kt % ST;
        if (kt < NKC - 1) asm volatile("cp.async.wait_group 1;\n" ::: "memory");
        else              asm volatile("cp.async.wait_group 0;\n" ::: "memory");
        __syncthreads();

        if (kt + 2 < NKC)
            load_chunk(sbase, kt + 2, (kt + 2) % ST, bm0, bn0, tid);

        #pragma unroll
        for (int ks = 0; ks < 2; ks++) {     // two k32 steps per 64-byte chunk
            uint32_t af[4][4], bb[2][4];
            const uint32_t abase =
                sbase + s * A_BYTES + (wm * 64 + lr) * ASTRB + ks * 32 + lh;
            #pragma unroll
            for (int mt = 0; mt < 4; mt++)
                ldsm4(af[mt], abase + mt * 16 * ASTRB);
            const uint32_t bbase =
                sbase + B_OFF + s * B_BYTES + (wn * 32 + lr) * ASTRB + ks * 32 + lh;
            #pragma unroll
            for (int p = 0; p < 2; p++)
                ldsm4(bb[p], bbase + p * 16 * ASTRB);

            #pragma unroll
            for (int mt = 0; mt < 4; mt++)
                #pragma unroll
                for (int nt = 0; nt < 4; nt++) {
                    uint32_t bfr[2] = { bb[nt >> 1][nt & 1], bb[nt >> 1][2 + (nt & 1)] };
                    mma16832(acc[mt][nt], af[mt], bfr);
                }
        }
    }

    // descale (inputs were x16 each)
    #pragma unroll
    for (int mt = 0; mt < 4; mt++)
        #pragma unroll
        for (int nt = 0; nt < 4; nt++)
            #pragma unroll
            for (int k = 0; k < 4; k++) acc[mt][nt][k] *= DESCALE;

    // ---- fused per-column sum(v^4) over this warp's 64 rows ----
    #pragma unroll
    for (int nt = 0; nt < 4; nt++) {
        float se = 0.f, so = 0.f;
        #pragma unroll
        for (int mt = 0; mt < 4; mt++) {
            float a0 = acc[mt][nt][0], a1 = acc[mt][nt][1];
            float a2 = acc[mt][nt][2], a3 = acc[mt][nt][3];
            se = fmaf(a0 * a0, a0 * a0, se); se = fmaf(a2 * a2, a2 * a2, se);
            so = fmaf(a1 * a1, a1 * a1, so); so = fmaf(a3 * a3, a3 * a3, so);
        }
        #pragma unroll
        for (int m = 4; m <= 16; m <<= 1) {   // reduce over lane>>2 (same lane&3)
            se += __shfl_xor_sync(0xffffffffu, se, m);
            so += __shfl_xor_sync(0xffffffffu, so, m);
        }
        if (lane < 4) {
            int c = bn0 + wn * 32 + nt * 8 + lane * 2;
            int slot = blockIdx.y * 2 + wm;
            g_s4part[slot][c]     = se;
            g_s4part[slot][c + 1] = so;
        }
    }

    // ---- epilogue: stage fp16 tile in smem, write coalesced rows ----
    __syncthreads();                       // smem ring no longer needed
    __half* sst = (__half*)smem;
    #pragma unroll
    for (int mt = 0; mt < 4; mt++) {
        #pragma unroll
        for (int nt = 0; nt < 4; nt++) {
            const int r = wm * 64 + mt * 16 + (lane >> 2);
            const int c = wn * 32 + nt * 8 + (lane & 3) * 2;
            *(__half2*)&sst[r * CSTR + c] =
                __floats2half2_rn(acc[mt][nt][0], acc[mt][nt][1]);
            *(__half2*)&sst[(r + 8) * CSTR + c] =
                __floats2half2_rn(acc[mt][nt][2], acc[mt][nt][3]);
        }
    }
    __syncthreads();
    #pragma unroll
    for (int i = 0; i < 16; i++) {
        const int r = warp * 16 + i;
        uint2 v = *(const uint2*)&sst[r * CSTR + lane * 4];
        *(uint2*)&g_conh[(size_t)(bm0 + r) * NB + bn0 + lane * 4] = v;
    }
}

// ---------------- norm finalize: inv 4-norm per column ----------------------
__global__ void norm_finalize() {
    int b = blockIdx.x * 256 + threadIdx.x;
    float s = 0.f;
    #pragma unroll
    for (int i = 0; i < 128; i++) s += g_s4part[i][b];
    float nrm = sqrtf(sqrtf(s));
    nrm = fmaxf(nrm, 1e-12f);
    g_inv_norm[b] = 1.0f / nrm;
}

// ---------------- pass B: per-column exp sums via fp16 ex2 ------------------
// 4 columns per thread, 32 rows per block. grid (NB/1024, NN/32) = (4, 256).
#define LOG2E 1.4426950408889634f

__global__ void exp_pass(const int* __restrict__ y) {
    __shared__ __half2 sy2[32];
    if (threadIdx.x < 32)
        sy2[threadIdx.x] = __float2half2_rn((float)__ldg(&y[blockIdx.y * 32 + threadIdx.x]));
    __syncthreads();

    const int b0 = blockIdx.x * 1024 + threadIdx.x * 4;
    const int n0 = blockIdx.y * 32;
    const float4 invf = *(const float4*)&g_inv_norm[b0];
    const __half2 inv01 = __floats2half2_rn(invf.x * LOG2E, invf.y * LOG2E);
    const __half2 inv23 = __floats2half2_rn(invf.z * LOG2E, invf.w * LOG2E);
    const __half* p = g_conh + (size_t)n0 * NB + b0;

    __half2 z01 = __float2half2_rn(0.f), z23 = z01, w01 = z01, w23 = z01;
    #pragma unroll 8
    for (int i = 0; i < 32; i++) {
        uint2 v = *(const uint2*)(p + (size_t)i * NB);
        __half2 h01 = *reinterpret_cast<__half2*>(&v.x);
        __half2 h23 = *reinterpret_cast<__half2*>(&v.y);
        __half2 e01 = hex2(__hmul2(h01, inv01));
        __half2 e23 = hex2(__hmul2(h23, inv23));
        __half2 m = sy2[i];
        z01 = __hadd2(z01, e01);
        z23 = __hadd2(z23, e23);
        w01 = __hfma2(m, e01, w01);
        w23 = __hfma2(m, e23, w23);
    }
    float2 fz01 = __half22float2(z01), fz23 = __half22float2(z23);
    float2 fw01 = __half22float2(w01), fw23 = __half22float2(w23);
    *(float4*)&g_zpart[blockIdx.y][b0] = make_float4(fz01.x, fz01.y, fz23.x, fz23.y);
    *(float4*)&g_wpart[blockIdx.y][b0] = make_float4(fw01.x, fw01.y, fw23.x, fw23.y);
}

// ---------------- final: sigmoid( sum_s theta*wsum / Z + bias ) -------------
__global__ void final_kernel(const float* __restrict__ bias, float* __restrict__ out) {
    int b = blockIdx.x * 256 + threadIdx.x;
    float Z = 0.f;
    #pragma unroll
    for (int i = 0; i < 256; i++) Z += g_zpart[i][b];
    float sum = 0.f;
    #pragma unroll
    for (int s = 0; s < NS; s++) {
        float w = 0.f;
        #pragma unroll
        for (int i = 0; i < 64; i++) w += g_wpart[s * 64 + i][b];
        sum += w * g_theta[s][b];
    }
    float r = sum / Z + bias[0];
    out[b] = 1.0f / (1.0f + expf(-r));
}

// ---------------- launch -----------------------------------------------------
extern "C" void kernel_launch(void* const* d_in, const int* in_sizes, int n_in,
                              void* d_out, int out_size) {
    const float* x = nullptr; const float* cat = nullptr; const float* phi = nullptr;
    const float* bias = nullptr; const int* y = nullptr;
    for (int i = 0; i < n_in; i++) {
        switch (in_sizes[i]) {
            case NB * ND: x    = (const float*)d_in[i]; break;
            case NN * ND: cat  = (const float*)d_in[i]; break;
            case NN:      y    = (const int*)d_in[i];   break;
            case NS * ND: phi  = (const float*)d_in[i]; break;
            case 1:       bias = (const float*)d_in[i]; break;
            default: break;
        }
    }
    float* out = (float*)d_out;

    cudaFuncSetAttribute(gemm_kernel, cudaFuncAttributeMaxDynamicSharedMemorySize, SM_TOTAL);

    convert_theta_kernel<<<NCONV + 512, 256>>>(cat, x, phi);
    gemm_kernel<<<dim3(NB / BN, NN / BM), 256, SM_TOTAL>>>();
    norm_finalize<<<NB / 256, 256>>>();
    exp_pass<<<dim3(NB / 1024, NN / 32), 256>>>(y);
    final_kernel<<<NB / 256, 256>>>(bias, out);
}

// round 17
// speedup vs baseline: 1.9888x; 1.0486x over previous
#include <cuda_runtime.h>
#include <cuda_fp16.h>
#include <cuda_fp8.h>
#include <cstdint>
#include <cstddef>

// Problem constants
#define NB 4096   // batch B
#define ND 768    // embedding D
#define NN 8192   // cat rows N
#define NS 4      // sources S

// ---------------- scratch (device globals; no allocations allowed) ----------
__device__ uint8_t g_cat8[NN * ND];                    // 6 MB (e4m3, x16 scale)
__device__ uint8_t g_x8[NB * ND];                      // 3 MB
__device__ uint8_t g_con8[(size_t)NN * NB];            // 32 MB (e4m3 con, unscaled)
__device__ float g_s4part[128][NB];                    // norm4 partials
__device__ float g_inv_norm[NB];
__device__ float g_zpart[256][NB];                     // softmax denom partials
__device__ float g_wpart[256][NB];                     // y-weighted partials
__device__ float g_theta[NS][NB];

// ---------------- helpers ----------------------------------------------------
__device__ __forceinline__ uint32_t smem_u32(const void* p) {
    uint32_t a;
    asm("{ .reg .u64 t; cvta.to.shared.u64 t, %1; cvt.u32.u64 %0, t; }" : "=r"(a) : "l"(p));
    return a;
}

__device__ __forceinline__ void cp16(uint32_t smem, const void* gmem) {
    asm volatile("cp.async.cg.shared.global [%0], [%1], 16;\n" :: "r"(smem), "l"(gmem));
}

__device__ __forceinline__ void ldsm4(uint32_t* r, uint32_t addr) {
    asm volatile("ldmatrix.sync.aligned.m8n8.x4.shared.b16 {%0,%1,%2,%3}, [%4];"
                 : "=r"(r[0]), "=r"(r[1]), "=r"(r[2]), "=r"(r[3]) : "r"(addr));
}

// FP8 e4m3 MMA, m16n8k32, fp32 accumulate (fastest legacy tensor path on sm_103)
__device__ __forceinline__ void mma16832(float* c, const uint32_t* a, const uint32_t* b) {
    asm volatile(
        "mma.sync.aligned.m16n8k32.row.col.f32.e4m3.e4m3.f32 "
        "{%0,%1,%2,%3}, {%4,%5,%6,%7}, {%8,%9}, {%0,%1,%2,%3};\n"
        : "+f"(c[0]), "+f"(c[1]), "+f"(c[2]), "+f"(c[3])
        : "r"(a[0]), "r"(a[1]), "r"(a[2]), "r"(a[3]), "r"(b[0]), "r"(b[1]));
}

__device__ __forceinline__ __half2 hex2(__half2 v) {
    __half2 r;
    asm("ex2.approx.f16x2 %0, %1;"
        : "=r"(*reinterpret_cast<uint32_t*>(&r))
        : "r"(*reinterpret_cast<const uint32_t*>(&v)));
    return r;
}

// ---------------- convert fp32 -> e4m3 (x16 scale) + theta ------------------
#define QSCALE 16.0f
#define DESCALE (1.0f / 256.0f)
#define NCONV ((NN * ND + NB * ND) / 4 / 256)   // 9216 convert blocks

__device__ __forceinline__ uint32_t pack_fp8x4(float4 v) {
    __nv_fp8x2_storage_t lo = __nv_cvt_float2_to_fp8x2(
        make_float2(v.x * QSCALE, v.y * QSCALE), __NV_SATFINITE, __NV_E4M3);
    __nv_fp8x2_storage_t hi = __nv_cvt_float2_to_fp8x2(
        make_float2(v.z * QSCALE, v.w * QSCALE), __NV_SATFINITE, __NV_E4M3);
    return (uint32_t)lo | ((uint32_t)hi << 16);
}

__global__ void convert_theta_kernel(const float* __restrict__ cat,
                                     const float* __restrict__ x,
                                     const float* __restrict__ phi) {
    if (blockIdx.x >= NCONV) {
        // theta: one warp per batch column; 512 blocks x 8 warps = 4096
        const int warp = threadIdx.x >> 5;
        const int lane = threadIdx.x & 31;
        const int b = (blockIdx.x - NCONV) * 8 + warp;
        const float* xr = x + (size_t)b * ND;
        float xv[24];
        #pragma unroll
        for (int i = 0; i < 24; i++) xv[i] = xr[lane + i * 32];
        #pragma unroll
        for (int s = 0; s < NS; s++) {
            const float* pr = phi + (size_t)s * ND;
            float acc = 0.f;
            #pragma unroll
            for (int i = 0; i < 24; i++) acc = fmaf(xv[i], pr[lane + i * 32], acc);
            #pragma unroll
            for (int off = 16; off; off >>= 1)
                acc += __shfl_xor_sync(0xffffffffu, acc, off);
            if (lane == 0) g_theta[s][b] = expf(acc);
        }
        return;
    }
    int i = blockIdx.x * blockDim.x + threadIdx.x;
    const int totCat = NN * ND / 4;
    if (i < totCat) {
        ((uint32_t*)g_cat8)[i] = pack_fp8x4(((const float4*)cat)[i]);
    } else {
        int j = i - totCat;
        ((uint32_t*)g_x8)[j] = pack_fp8x4(((const float4*)x)[j]);
    }
}

// ---------------- GEMM: con[N,B] = cat[N,D] @ x[B,D]^T  (FP8) ---------------
// 128x128 CTA tile, 8 warps (2x4) at 64x32 each, K-chunk 64 fp8, 3-stage ring,
// 2 CTAs/SM.
#define BM 128
#define BN 128
#define BKB 64                  // fp8 elements (= bytes) per K chunk
#define NKC (ND / BKB)          // 12
#define ST 3
#define ASTRB 80                // bytes per smem row (64 + 16 pad) — CF for ldsm & cp
#define A_BYTES (BM * ASTRB)    // 10240
#define B_BYTES (BN * ASTRB)    // 10240
#define B_OFF (ST * A_BYTES)    // 30720
#define SM_TOTAL (ST * (A_BYTES + B_BYTES))            // 61440
#define CSTRB 136               // epilogue staging stride (bytes, fp8 tile)

__device__ __forceinline__ void load_chunk(uint32_t sbase, int kt, int s,
                                           int bm0, int bn0, int tid) {
    const int k0 = kt * BKB;
    #pragma unroll
    for (int t = 0; t < 2; t++) {            // A: 128 rows x 4 x 16B
        int idx = tid + t * 256;
        int row = idx >> 2, c = (idx & 3) * 16;
        const void* g = g_cat8 + (size_t)(bm0 + row) * ND + k0 + c;
        cp16(sbase + s * A_BYTES + row * ASTRB + c, g);
    }
    #pragma unroll
    for (int t = 0; t < 2; t++) {            // B: 128 rows x 4 x 16B
        int idx = tid + t * 256;
        int row = idx >> 2, c = (idx & 3) * 16;
        const void* g = g_x8 + (size_t)(bn0 + row) * ND + k0 + c;
        cp16(sbase + B_OFF + s * B_BYTES + row * ASTRB + c, g);
    }
    asm volatile("cp.async.commit_group;\n" ::: "memory");
}

__global__ void __launch_bounds__(256, 2) gemm_kernel() {
    extern __shared__ char smem[];
    const uint32_t sbase = smem_u32(smem);

    const int tid  = threadIdx.x;
    const int lane = tid & 31;
    const int warp = tid >> 5;
    const int wm   = warp & 1;     // 2 warp rows (64 each)
    const int wn   = warp >> 1;    // 4 warp cols (32 each)
    const int bm0  = blockIdx.y * BM;    // n offset
    const int bn0  = blockIdx.x * BN;    // b offset

    const int lr = lane & 15;            // ldmatrix row within 16-row tile
    const int lh = (lane >> 4) * 16;     // 16-byte half select

    float acc[4][4][4];
    #pragma unroll
    for (int mt = 0; mt < 4; mt++)
        #pragma unroll
        for (int nt = 0; nt < 4; nt++)
            #pragma unroll
            for (int k = 0; k < 4; k++) acc[mt][nt][k] = 0.f;

    load_chunk(sbase, 0, 0, bm0, bn0, tid);
    load_chunk(sbase, 1, 1, bm0, bn0, tid);

    for (int kt = 0; kt < NKC; kt++) {
        const int s = kt % ST;
        if (kt < NKC - 1) asm volatile("cp.async.wait_group 1;\n" ::: "memory");
        else              asm volatile("cp.async.wait_group 0;\n" ::: "memory");
        __syncthreads();

        if (kt + 2 < NKC)
            load_chunk(sbase, kt + 2, (kt + 2) % ST, bm0, bn0, tid);

        #pragma unroll
        for (int ks = 0; ks < 2; ks++) {     // two k32 steps per 64-byte chunk
            uint32_t af[4][4], bb[2][4];
            const uint32_t abase =
                sbase + s * A_BYTES + (wm * 64 + lr) * ASTRB + ks * 32 + lh;
            #pragma unroll
            for (int mt = 0; mt < 4; mt++)
                ldsm4(af[mt], abase + mt * 16 * ASTRB);
            const uint32_t bbase =
                sbase + B_OFF + s * B_BYTES + (wn * 32 + lr) * ASTRB + ks * 32 + lh;
            #pragma unroll
            for (int p = 0; p < 2; p++)
                ldsm4(bb[p], bbase + p * 16 * ASTRB);

            #pragma unroll
            for (int mt = 0; mt < 4; mt++)
                #pragma unroll
                for (int nt = 0; nt < 4; nt++) {
                    uint32_t bfr[2] = { bb[nt >> 1][nt & 1], bb[nt >> 1][2 + (nt & 1)] };
                    mma16832(acc[mt][nt], af[mt], bfr);
                }
        }
    }

    // descale (inputs were x16 each)
    #pragma unroll
    for (int mt = 0; mt < 4; mt++)
        #pragma unroll
        for (int nt = 0; nt < 4; nt++)
            #pragma unroll
            for (int k = 0; k < 4; k++) acc[mt][nt][k] *= DESCALE;

    // ---- fused per-column sum(v^4) over this warp's 64 rows (fp32, exact) ----
    #pragma unroll
    for (int nt = 0; nt < 4; nt++) {
        float se = 0.f, so = 0.f;
        #pragma unroll
        for (int mt = 0; mt < 4; mt++) {
            float a0 = acc[mt][nt][0], a1 = acc[mt][nt][1];
            float a2 = acc[mt][nt][2], a3 = acc[mt][nt][3];
            se = fmaf(a0 * a0, a0 * a0, se); se = fmaf(a2 * a2, a2 * a2, se);
            so = fmaf(a1 * a1, a1 * a1, so); so = fmaf(a3 * a3, a3 * a3, so);
        }
        #pragma unroll
        for (int m = 4; m <= 16; m <<= 1) {   // reduce over lane>>2 (same lane&3)
            se += __shfl_xor_sync(0xffffffffu, se, m);
            so += __shfl_xor_sync(0xffffffffu, so, m);
        }
        if (lane < 4) {
            int c = bn0 + wn * 32 + nt * 8 + lane * 2;
            int slot = blockIdx.y * 2 + wm;
            g_s4part[slot][c]     = se;
            g_s4part[slot][c + 1] = so;
        }
    }

    // ---- epilogue: stage e4m3 tile in smem, write coalesced rows ----
    __syncthreads();                       // smem ring no longer needed
    uint8_t* sst = (uint8_t*)smem;
    #pragma unroll
    for (int mt = 0; mt < 4; mt++) {
        #pragma unroll
        for (int nt = 0; nt < 4; nt++) {
            const int r = wm * 64 + mt * 16 + (lane >> 2);
            const int c = wn * 32 + nt * 8 + (lane & 3) * 2;
            *(uint16_t*)&sst[r * CSTRB + c] = (uint16_t)__nv_cvt_float2_to_fp8x2(
                make_float2(acc[mt][nt][0], acc[mt][nt][1]), __NV_SATFINITE, __NV_E4M3);
            *(uint16_t*)&sst[(r + 8) * CSTRB + c] = (uint16_t)__nv_cvt_float2_to_fp8x2(
                make_float2(acc[mt][nt][2], acc[mt][nt][3]), __NV_SATFINITE, __NV_E4M3);
        }
    }
    __syncthreads();
    #pragma unroll
    for (int i = 0; i < 16; i++) {
        const int r = warp * 16 + i;
        uint32_t v = *(const uint32_t*)&sst[r * CSTRB + lane * 4];
        *(uint32_t*)&g_con8[(size_t)(bm0 + r) * NB + bn0 + lane * 4] = v;
    }
}

// ---------------- norm finalize: inv 4-norm per column ----------------------
__global__ void norm_finalize() {
    int b = blockIdx.x * 256 + threadIdx.x;
    float s = 0.f;
    #pragma unroll
    for (int i = 0; i < 128; i++) s += g_s4part[i][b];
    float nrm = sqrtf(sqrtf(s));
    nrm = fmaxf(nrm, 1e-12f);
    g_inv_norm[b] = 1.0f / nrm;
}

// ---------------- pass B: per-column exp sums via fp16 ex2 ------------------
// 4 columns per thread, 32 rows per block. grid (NB/1024, NN/32) = (4, 256).
#define LOG2E 1.4426950408889634f

__global__ void exp_pass(const int* __restrict__ y) {
    __shared__ __half2 sy2[32];
    if (threadIdx.x < 32)
        sy2[threadIdx.x] = __float2half2_rn((float)__ldg(&y[blockIdx.y * 32 + threadIdx.x]));
    __syncthreads();

    const int b0 = blockIdx.x * 1024 + threadIdx.x * 4;
    const int n0 = blockIdx.y * 32;
    const float4 invf = *(const float4*)&g_inv_norm[b0];
    const __half2 inv01 = __floats2half2_rn(invf.x * LOG2E, invf.y * LOG2E);
    const __half2 inv23 = __floats2half2_rn(invf.z * LOG2E, invf.w * LOG2E);
    const uint8_t* p = g_con8 + (size_t)n0 * NB + b0;

    __half2 z01 = __float2half2_rn(0.f), z23 = z01, w01 = z01, w23 = z01;
    #pragma unroll 8
    for (int i = 0; i < 32; i++) {
        uint32_t v = *(const uint32_t*)(p + (size_t)i * NB);
        __half2 h01 = __half2(__nv_cvt_fp8x2_to_halfraw2(
            (__nv_fp8x2_storage_t)(v & 0xFFFFu), __NV_E4M3));
        __half2 h23 = __half2(__nv_cvt_fp8x2_to_halfraw2(
            (__nv_fp8x2_storage_t)(v >> 16), __NV_E4M3));
        __half2 e01 = hex2(__hmul2(h01, inv01));
        __half2 e23 = hex2(__hmul2(h23, inv23));
        __half2 m = sy2[i];
        z01 = __hadd2(z01, e01);
        z23 = __hadd2(z23, e23);
        w01 = __hfma2(m, e01, w01);
        w23 = __hfma2(m, e23, w23);
    }
    float2 fz01 = __half22float2(z01), fz23 = __half22float2(z23);
    float2 fw01 = __half22float2(w01), fw23 = __half22float2(w23);
    *(float4*)&g_zpart[blockIdx.y][b0] = make_float4(fz01.x, fz01.y, fz23.x, fz23.y);
    *(float4*)&g_wpart[blockIdx.y][b0] = make_float4(fw01.x, fw01.y, fw23.x, fw23.y);
}

// ---------------- final: sigmoid( sum_s theta*wsum / Z + bias ) -------------
__global__ void final_kernel(const float* __restrict__ bias, float* __restrict__ out) {
    int b = blockIdx.x * 256 + threadIdx.x;
    float Z = 0.f;
    #pragma unroll
    for (int i = 0; i < 256; i++) Z += g_zpart[i][b];
    float sum = 0.f;
    #pragma unroll
    for (int s = 0; s < NS; s++) {
        float w = 0.f;
        #pragma unroll
        for (int i = 0; i < 64; i++) w += g_wpart[s * 64 + i][b];
        sum += w * g_theta[s][b];
    }
    float r = sum / Z + bias[0];
    out[b] = 1.0f / (1.0f + expf(-r));
}

// ---------------- launch -----------------------------------------------------
extern "C" void kernel_launch(void* const* d_in, const int* in_sizes, int n_in,
                              void* d_out, int out_size) {
    const float* x = nullptr; const float* cat = nullptr; const float* phi = nullptr;
    const float* bias = nullptr; const int* y = nullptr;
    for (int i = 0; i < n_in; i++) {
        switch (in_sizes[i]) {
            case NB * ND: x    = (const float*)d_in[i]; break;
            case NN * ND: cat  = (const float*)d_in[i]; break;
            case NN:      y    = (const int*)d_in[i];   break;
            case NS * ND: phi  = (const float*)d_in[i]; break;
            case 1:       bias = (const float*)d_in[i]; break;
            default: break;
        }
    }
    float* out = (float*)d_out;

    cudaFuncSetAttribute(gemm_kernel, cudaFuncAttributeMaxDynamicSharedMemorySize, SM_TOTAL);

    convert_theta_kernel<<<NCONV + 512, 256>>>(cat, x, phi);
    gemm_kernel<<<dim3(NB / BN, NN / BM), 256, SM_TOTAL>>>();
    norm_finalize<<<NB / 256, 256>>>();
    exp_pass<<<dim3(NB / 1024, NN / 32), 256>>>(y);
    final_kernel<<<NB / 256, 256>>>(bias, out);
}